// round 4
// baseline (speedup 1.0000x reference)
#include <cuda_runtime.h>

#define LOG2E 1.4426950408889634f
#define EPS   1e-8f

__device__ float        g_partials[8192];
__device__ unsigned int g_done;   // zero-init; last block resets -> graph-replay safe

__device__ __forceinline__ float ex2_approx(float x) {
    float r; asm("ex2.approx.ftz.f32 %0, %1;" : "=f"(r) : "f"(x)); return r;
}
__device__ __forceinline__ float lg2_approx(float x) {
    float r; asm("lg2.approx.ftz.f32 %0, %1;" : "=f"(r) : "f"(x)); return r;
}

// One block per row. 256 threads: i = tid & 127 (doc index), h = tid >> 7
// (k-parity group). Group h covers cyclic distances k = 1+h, 3+h, ... <= halfm.
__global__ void __launch_bounds__(256) ndcg_fused_kernel(
    const float* __restrict__ scores,
    const int*   __restrict__ relev,
    const int*   __restrict__ qlen,
    float*       __restrict__ out,
    int D, int B)
{
    const int tid = threadIdx.x;
    const int b   = blockIdx.x;
    const int i   = tid & 127;
    const int h   = tid >> 7;

    __shared__ float2 s_sg[128];   // (score, gain)
    __shared__ int    s_cnt[8];
    __shared__ float  s_rnum[8];
    __shared__ float  s_ridl[8];
    __shared__ int    s_last;

    const int  L     = qlen[b];
    const bool valid = (i < L);

    // group 0 loads from global and stages smem + histogram
    if (h == 0) {
        const float sv = scores[b * D + i];
        const int   rv = relev[b * D + i];
        const float gv = valid ? (float)((1 << rv) - 1) : 0.0f;  // 2^rel - 1
        s_sg[i] = make_float2(sv, gv);
        if (i < 8) s_cnt[i] = 0;
    }
    __syncthreads();
    if (h == 0 && valid) {
        atomicAdd(&s_cnt[relev[b * D + i]], 1);
    }

    const float2 me = s_sg[i];
    const float  si = me.x;
    const float  gi = me.y;
    __syncthreads();

    // ---- pairwise sum over unordered valid pairs (cyclic-distance enum) ----
    // pair {i,j}, a=|si-sj|: both-orders folded contribution
    //   -delta * (a*log2e + 2*log2(1 + 2^{-a*log2e}))
    float num = 0.0f;
    if (valid && L > 1) {
        const int halfm = (L - 1) >> 1;
        #pragma unroll 4
        for (int k = 1 + h; k <= halfm; k += 2) {
            int j = i + k; if (j >= L) j -= L;
            const float2 p  = s_sg[j];
            const float a     = fabsf(si - p.x);
            const float delta = fabsf(gi - p.y);
            const float nm = a * (-LOG2E);
            const float u  = ex2_approx(nm);           // MUFU.EX2
            const float l  = lg2_approx(1.0f + u);     // MUFU.LG2
            num = fmaf(-delta, fmaf(2.0f, l, -nm), num);
        }
        // tie distance k=L/2 (L even): counted once, by group 0, i < L/2
        if ((h == 0) && ((L & 1) == 0) && (i < (L >> 1))) {
            const float2 p  = s_sg[i + (L >> 1)];
            const float a     = fabsf(si - p.x);
            const float delta = fabsf(gi - p.y);
            const float nm = a * (-LOG2E);
            const float u  = ex2_approx(nm);
            const float l  = lg2_approx(1.0f + u);
            num = fmaf(-delta, fmaf(2.0f, l, -nm), num);
        }
    }

    // ---- ideal DCG via counting sort (gains in {0,1,3,7,15}), group 0 only ----
    float idl = 0.0f;
    if (h == 0 && valid) {
        const int c4 = s_cnt[4];
        const int c3 = c4 + s_cnt[3];
        const int c2 = c3 + s_cnt[2];
        const int c1 = c2 + s_cnt[1];
        float gr;
        if      (i < c4) gr = 15.0f;
        else if (i < c3) gr = 7.0f;
        else if (i < c2) gr = 3.0f;
        else if (i < c1) gr = 1.0f;
        else             gr = 0.0f;
        idl = gr / lg2_approx((float)(i + 2));
    }

    // ---- block reduction of (num, idl) across 8 warps ----
    #pragma unroll
    for (int off = 16; off > 0; off >>= 1) {
        num += __shfl_down_sync(0xFFFFFFFFu, num, off);
        idl += __shfl_down_sync(0xFFFFFFFFu, idl, off);
    }
    const int wid  = tid >> 5;
    const int lane = tid & 31;
    if (lane == 0) { s_rnum[wid] = num; s_ridl[wid] = idl; }
    __syncthreads();
    if (tid == 0) {
        float n = 0.0f, id = 0.0f;
        #pragma unroll
        for (int w = 0; w < 8; ++w) { n += s_rnum[w]; id += s_ridl[w]; }
        g_partials[b] = -n / (id + EPS);
        __threadfence();
        unsigned int t = atomicAdd(&g_done, 1u);
        s_last = (t == (unsigned int)(gridDim.x - 1));
    }
    __syncthreads();

    // ---- last block: deterministic final reduction ----
    if (s_last) {
        __threadfence();
        float s = 0.0f;
        for (int r = tid; r < B; r += 256) s += g_partials[r];
        #pragma unroll
        for (int off = 16; off > 0; off >>= 1)
            s += __shfl_down_sync(0xFFFFFFFFu, s, off);
        if (lane == 0) s_rnum[wid] = s;
        __syncthreads();
        if (tid == 0) {
            float t = 0.0f;
            #pragma unroll
            for (int w = 0; w < 8; ++w) t += s_rnum[w];
            out[0] = t / (float)B;
            g_done = 0;   // reset for next replay
        }
    }
}

extern "C" void kernel_launch(void* const* d_in, const int* in_sizes, int n_in,
                              void* d_out, int out_size)
{
    const float* scores = (const float*)d_in[0];
    const int*   relev  = (const int*)  d_in[1];
    const int*   qlen   = (const int*)  d_in[2];
    float*       out    = (float*)      d_out;

    const int B = in_sizes[2];
    const int D = in_sizes[0] / B;   // 128

    ndcg_fused_kernel<<<B, 256>>>(scores, relev, qlen, out, D, B);
}